// round 3
// baseline (speedup 1.0000x reference)
#include <cuda_runtime.h>

// RoIMaskAlign: features (B=2, C=256, H=200, W=272) fp32, rois (K=256, 5) fp32
// out (K, C, 14, 14) fp32
// PH=PW=14, SPATIAL_SCALE=0.25, SR=2, SPATIAL_SHIFT=0, HALF_PART=0, ROI_SCALE=1.2

#define PH 14
#define PW 14

static constexpr int   Cc = 256;
static constexpr int   Hc = 200;
static constexpr int   Wc = 272;
static constexpr float SCALE     = 0.25f;
static constexpr float ROI_SCALE = 1.2f;

static constexpr int SEGS = 2 * PH * 2;   // 56 row segments: (ph,sy) x {y0, y0+1}
static constexpr int MAXW = 136;          // max x-window width (bound is ~129)
static constexpr int STR  = 137;          // odd stride -> bank-conflict friendly

__global__ __launch_bounds__(256)
void roi_mask_align_kernel(const float* __restrict__ feat,
                           const float* __restrict__ rois,
                           float* __restrict__ out)
{
    __shared__ float s_tile[SEGS * STR];   // 56*137*4 = 30688 B

    int nc = blockIdx.x;               // 0 .. K*C-1
    int c  = nc & (Cc - 1);
    int n  = nc >> 8;                  // Cc == 256
    int t    = threadIdx.x;            // 0..255
    int wid  = t >> 5;                 // 0..7
    int lane = t & 31;

    // ---- ROI params (identical computation in every thread) ----
    const float* r = rois + n * 5;
    int   b  = (int)r[0];
    float rx1 = r[1], ry1 = r[2], rx2 = r[3], ry2 = r[4];

    float cx = (rx1 + rx2) * 0.5f;
    float cy = (ry1 + ry2) * 0.5f;
    float w  = (rx2 - rx1) * ROI_SCALE;
    float h  = (ry2 - ry1) * ROI_SCALE;
    float x1s = (cx - 0.5f * w) * SCALE;
    float x2s = (cx + 0.5f * w) * SCALE;
    float y1s = (cy - 0.5f * h) * SCALE;
    float y2s = (cy + 0.5f * h) * SCALE;

    float roi_w = fmaxf(x2s - x1s, 1.0f);
    float roi_h = fmaxf(y2s - y1s, 1.0f);
    float bin_w = roi_w * (1.0f / PW);
    float bin_h = roi_h * (1.0f / PH);

    const float* fb = feat + ((size_t)(b * Cc + c)) * (Hc * Wc);

    // ---- x-window of the block (same in all threads; matches sample formulas) ----
    // first sample: pw=0, sx=0 -> x1s + 0.25*bin_w ; last: pw=13, sx=1 -> x1s + 13.75*bin_w
    float xf = x1s + 0.25f  * bin_w;
    float xl = x1s + 13.75f * bin_w;
    int xlo = (int)floorf(fminf(fmaxf(xf, 0.0f), (float)(Wc - 1)));
    int xhi = min((int)floorf(fminf(fmaxf(xl, 0.0f), (float)(Wc - 1))) + 1, Wc - 1);
    int width = xhi - xlo + 1;         // <= ~129 < MAXW

    // ---- stage 56 row segments, coalesced ----
    for (int s = wid; s < SEGS; s += 8) {
        int j    = (s >= 28) ? (s - 28) : s;
        int plus = (s >= 28) ? 1 : 0;
        int ph_s = j >> 1;
        int sy_s = j & 1;
        float y = y1s + ((float)ph_s + (sy_s ? 0.75f : 0.25f)) * bin_h;
        float yc = fminf(fmaxf(y, 0.0f), (float)(Hc - 1));
        int y0 = (int)floorf(yc);
        int row = plus ? min(y0 + 1, Hc - 1) : y0;
        const float* src = fb + (size_t)row * Wc + xlo;
        float* dst = s_tile + s * STR;
        for (int x = lane; x < width; x += 32)
            dst[x] = __ldg(src + x);
    }
    __syncthreads();

    // ---- sampling ----
    if (t < PH * PW) {
        int pw = t % PW;
        int ph = t / PW;

        // per-sample x data (shared across sy)
        int   xi0[2], xi1[2];
        float lx[2], hx[2];
        bool  vx[2];
        #pragma unroll
        for (int sx = 0; sx < 2; sx++) {
            float x = x1s + ((float)pw + ((float)sx + 0.5f) * 0.5f) * bin_w;
            vx[sx] = (x > -1.0f) && (x < (float)Wc);
            float xc = fminf(fmaxf(x, 0.0f), (float)(Wc - 1));
            int x0 = (int)floorf(xc);
            xi0[sx] = x0 - xlo;
            xi1[sx] = min(x0 + 1, Wc - 1) - xlo;
            lx[sx] = xc - (float)x0;
            hx[sx] = 1.0f - lx[sx];
        }

        float sum = 0.0f;
        #pragma unroll
        for (int sy = 0; sy < 2; sy++) {
            float y = y1s + ((float)ph + (sy ? 0.75f : 0.25f)) * bin_h;
            bool vy = (y > -1.0f) && (y < (float)Hc);
            float yc = fminf(fmaxf(y, 0.0f), (float)(Hc - 1));
            int y0 = (int)floorf(yc);
            float ly = yc - (float)y0;
            float hy = 1.0f - ly;

            int j = ph * 2 + sy;
            const float* row0 = s_tile + j * STR;          // y0 segment
            const float* row1 = s_tile + (28 + j) * STR;   // y0+1 segment

            #pragma unroll
            for (int sx = 0; sx < 2; sx++) {
                float v00 = row0[xi0[sx]];
                float v01 = row0[xi1[sx]];
                float v10 = row1[xi0[sx]];
                float v11 = row1[xi1[sx]];
                float top = hx[sx] * v00 + lx[sx] * v01;
                float bot = hx[sx] * v10 + lx[sx] * v11;
                float val = hy * top + ly * bot;
                sum += (vy && vx[sx]) ? val : 0.0f;
            }
        }

        out[(size_t)nc * (PH * PW) + t] = sum * 0.25f;
    }
}

extern "C" void kernel_launch(void* const* d_in, const int* in_sizes, int n_in,
                              void* d_out, int out_size)
{
    const float* feat = (const float*)d_in[0];
    const float* rois = (const float*)d_in[1];
    float* out = (float*)d_out;

    int blocks = out_size / (PH * PW);   // K * C = 65536
    roi_mask_align_kernel<<<blocks, 256>>>(feat, rois, out);
}

// round 4
// speedup vs baseline: 2.7761x; 2.7761x over previous
#include <cuda_runtime.h>

// RoIMaskAlign: features (B=2, C=256, H=200, W=272) fp32, rois (K=256, 5) fp32
// out (K, C, 14, 14) fp32
// PH=PW=14, SPATIAL_SCALE=0.25, SR=2, SPATIAL_SHIFT=0, HALF_PART=0, ROI_SCALE=1.2

#define PH 14
#define PW 14

static constexpr int   Cc = 256;
static constexpr int   Hc = 200;
static constexpr int   Wc = 272;
static constexpr float SCALE     = 0.25f;
static constexpr float ROI_SCALE = 1.2f;

__global__ __launch_bounds__(256)
void roi_mask_align_kernel(const float* __restrict__ feat,
                           const float* __restrict__ rois,
                           float* __restrict__ out,
                           int total)
{
    int idx = blockIdx.x * blockDim.x + threadIdx.x;
    if (idx >= total) return;

    int pw = idx % PW;
    int t1 = idx / PW;
    int ph = t1 % PH;
    int t2 = t1 / PH;
    int c  = t2 % Cc;
    int n  = t2 / Cc;

    const float* r = rois + n * 5;
    int   b  = (int)r[0];
    float x1 = r[1], y1 = r[2], x2 = r[3], y2 = r[4];

    float cx = (x1 + x2) * 0.5f;
    float cy = (y1 + y2) * 0.5f;
    float w  = (x2 - x1) * ROI_SCALE;
    float h  = (y2 - y1) * ROI_SCALE;
    float x1s = (cx - 0.5f * w) * SCALE;
    float x2s = (cx + 0.5f * w) * SCALE;
    float y1s = (cy - 0.5f * h) * SCALE;
    float y2s = (cy + 0.5f * h) * SCALE;

    float roi_w = fmaxf(x2s - x1s, 1.0f);
    float roi_h = fmaxf(y2s - y1s, 1.0f);
    float bin_w = roi_w * (1.0f / PW);
    float bin_h = roi_h * (1.0f / PH);

    const float* fb = feat + ((size_t)(b * Cc + c)) * (Hc * Wc);

    // ---- per-sample x data (shared across both sy rows) ----
    // Pair trick: v00/v01 are at (x0, x0+1). Load 8B-aligned float2 at
    // base = x0 - (x0 & 1); if x0 odd, one predicated scalar fixes v01.
    int   base[2];     // even element index, 8B aligned (rows start even: W=272)
    int   xf[2];       // clamped x0+1, for the odd-case fixup
    bool  podd[2];     // x0 & 1
    float lx[2], hx[2];
    bool  vx[2];
    #pragma unroll
    for (int sx = 0; sx < 2; sx++) {
        float x = x1s + ((float)pw + ((float)sx + 0.5f) * 0.5f) * bin_w;
        vx[sx] = (x > -1.0f) && (x < (float)Wc);
        float xc = fminf(fmaxf(x, 0.0f), (float)(Wc - 1));
        int x0 = (int)floorf(xc);
        int p  = x0 & 1;
        podd[sx] = (p != 0);
        base[sx] = x0 - p;
        xf[sx]   = min(x0 + 1, Wc - 1);
        lx[sx] = xc - (float)x0;
        hx[sx] = 1.0f - lx[sx];
    }

    float sum = 0.0f;
    #pragma unroll
    for (int sy = 0; sy < 2; sy++) {
        float y = y1s + ((float)ph + (sy ? 0.75f : 0.25f)) * bin_h;
        bool vy = (y > -1.0f) && (y < (float)Hc);
        float yc = fminf(fmaxf(y, 0.0f), (float)(Hc - 1));
        int y0 = (int)floorf(yc);
        int y1b = min(y0 + 1, Hc - 1);
        float ly = yc - (float)y0;
        float hy = 1.0f - ly;

        const float* row0 = fb + (size_t)y0  * Wc;
        const float* row1 = fb + (size_t)y1b * Wc;

        // 4 paired loads (2 rows x 2 samples) — same bytes as 8 scalars,
        // half the L1 accesses. Issued together for MLP.
        float2 a00 = __ldg((const float2*)(row0 + base[0]));
        float2 a01 = __ldg((const float2*)(row0 + base[1]));
        float2 a10 = __ldg((const float2*)(row1 + base[0]));
        float2 a11 = __ldg((const float2*)(row1 + base[1]));

        // predicated fixups, only when x0 is odd (~50% of lanes per sx)
        float s00 = 0.f, s01 = 0.f, s10 = 0.f, s11 = 0.f;
        if (podd[0]) { s00 = __ldg(row0 + xf[0]); s10 = __ldg(row1 + xf[0]); }
        if (podd[1]) { s01 = __ldg(row0 + xf[1]); s11 = __ldg(row1 + xf[1]); }

        // sample sx=0
        {
            float v00 = podd[0] ? a00.y : a00.x;
            float v01 = podd[0] ? s00   : a00.y;
            float v10 = podd[0] ? a10.y : a10.x;
            float v11 = podd[0] ? s10   : a10.y;
            float top = hx[0] * v00 + lx[0] * v01;
            float bot = hx[0] * v10 + lx[0] * v11;
            sum += (vy && vx[0]) ? (hy * top + ly * bot) : 0.0f;
        }
        // sample sx=1
        {
            float v00 = podd[1] ? a01.y : a01.x;
            float v01 = podd[1] ? s01   : a01.y;
            float v10 = podd[1] ? a11.y : a11.x;
            float v11 = podd[1] ? s11   : a11.y;
            float top = hx[1] * v00 + lx[1] * v01;
            float bot = hx[1] * v10 + lx[1] * v11;
            sum += (vy && vx[1]) ? (hy * top + ly * bot) : 0.0f;
        }
    }

    out[idx] = sum * 0.25f;
}

extern "C" void kernel_launch(void* const* d_in, const int* in_sizes, int n_in,
                              void* d_out, int out_size)
{
    const float* feat = (const float*)d_in[0];
    const float* rois = (const float*)d_in[1];
    float* out = (float*)d_out;

    int total = out_size;  // K * C * PH * PW
    int threads = 256;
    int blocks = (total + threads - 1) / threads;
    roi_mask_align_kernel<<<blocks, threads>>>(feat, rois, out, total);
}

// round 5
// speedup vs baseline: 3.9869x; 1.4361x over previous
#include <cuda_runtime.h>
#include <cuda_fp16.h>

// RoIMaskAlign via NHWC-fp16 staging.
// features (B=2, C=256, H=200, W=272) fp32, rois (K, 5) fp32
// out (K, C, 14, 14) fp32
// PH=PW=14, SPATIAL_SCALE=0.25, SR=2, SPATIAL_SHIFT=0, HALF_PART=0, ROI_SCALE=1.2

#define PH 14
#define PW 14

static constexpr int   Bc = 2;
static constexpr int   Cc = 256;
static constexpr int   Hc = 200;
static constexpr int   Wc = 272;
static constexpr float SCALE     = 0.25f;
static constexpr float ROI_SCALE = 1.2f;

// NHWC fp16 scratch: (B, H, W, C) = 2*200*272*256 halves = 55.7 MB
__device__ __align__(16) __half g_nhwc[(size_t)Bc * Hc * Wc * Cc];

// ---------------------------------------------------------------------------
// Kernel 1: NCHW fp32 -> NHWC fp16 transpose.
// Block handles (b, y, 16-x tile) x all 256 channels. W = 272 = 17*16 exact.
// ---------------------------------------------------------------------------
__global__ __launch_bounds__(256)
void transpose_kernel(const float* __restrict__ feat)
{
    __shared__ __align__(16) __half s[16][264];   // [x][c], padded rows

    int x0 = blockIdx.x * 16;
    int y  = blockIdx.y;
    int b  = blockIdx.z;
    int tid = threadIdx.x;
    int xl = tid & 15;        // lane-major x -> coalesced 64B row segments
    int ci = tid >> 4;        // 0..15

    const float* fp = feat + (((size_t)b * Cc) * Hc + y) * Wc + x0 + xl;
    #pragma unroll
    for (int k = 0; k < 16; k++) {
        int c = k * 16 + ci;
        s[xl][c] = __float2half_rn(__ldg(fp + (size_t)c * (Hc * Wc)));
    }
    __syncthreads();

    // write: per x, 256 halves = 512B contiguous (32 uint4)
    __half* op = g_nhwc + (((size_t)b * Hc + y) * Wc + x0) * Cc;
    #pragma unroll
    for (int j = 0; j < 2; j++) {
        int u = tid + j * 256;     // 0..511
        int x = u >> 5;
        int k = u & 31;
        *reinterpret_cast<uint4*>(op + (size_t)x * Cc + k * 8) =
            *reinterpret_cast<const uint4*>(&s[x][k * 8]);
    }
}

// ---------------------------------------------------------------------------
// Kernel 2: gather. Block = (n, ph); 7 warps, warp w handles pw = 2w, 2w+1.
// Each tap loads the full 256-channel vector (512B) with one LDG.128 per lane.
// Lane owns channels c = 8*lane .. 8*lane+7.
// ---------------------------------------------------------------------------
__global__ __launch_bounds__(224)
void gather_kernel(const float* __restrict__ rois,
                   float* __restrict__ out)
{
    __shared__ __align__(16) float s[PW][264];   // [pw][c], padded

    int n  = blockIdx.x;
    int ph = blockIdx.y;
    int w    = threadIdx.x >> 5;
    int lane = threadIdx.x & 31;

    // ---- ROI geometry (warp-uniform) ----
    const float* r = rois + n * 5;
    int   b  = (int)r[0];
    float rx1 = r[1], ry1 = r[2], rx2 = r[3], ry2 = r[4];

    float cx = (rx1 + rx2) * 0.5f;
    float cy = (ry1 + ry2) * 0.5f;
    float rw = (rx2 - rx1) * ROI_SCALE;
    float rh = (ry2 - ry1) * ROI_SCALE;
    float x1s = (cx - 0.5f * rw) * SCALE;
    float x2s = (cx + 0.5f * rw) * SCALE;
    float y1s = (cy - 0.5f * rh) * SCALE;
    float y2s = (cy + 0.5f * rh) * SCALE;

    float roi_w = fmaxf(x2s - x1s, 1.0f);
    float roi_h = fmaxf(y2s - y1s, 1.0f);
    float bin_w = roi_w * (1.0f / PW);
    float bin_h = roi_h * (1.0f / PH);

    const __half* tb = g_nhwc;

    #pragma unroll
    for (int i = 0; i < 2; i++) {
        int pw = w * 2 + i;

        float a0=0.f,a1=0.f,a2=0.f,a3=0.f,a4=0.f,a5=0.f,a6=0.f,a7=0.f;

        // per-sample x data (shared across sy)
        int   xi0[2], xi1[2];
        float lx[2], hx[2];
        bool  vx[2];
        #pragma unroll
        for (int sx = 0; sx < 2; sx++) {
            float x = x1s + ((float)pw + ((float)sx + 0.5f) * 0.5f) * bin_w;
            vx[sx] = (x > -1.0f) && (x < (float)Wc);
            float xc = fminf(fmaxf(x, 0.0f), (float)(Wc - 1));
            int x0 = (int)floorf(xc);
            xi0[sx] = x0;
            xi1[sx] = min(x0 + 1, Wc - 1);
            lx[sx] = xc - (float)x0;
            hx[sx] = 1.0f - lx[sx];
        }

        #define TAP(pix, wt) do {                                               \
            if ((wt) != 0.0f) {                                                 \
                uint4 v = *reinterpret_cast<const uint4*>(                      \
                    tb + (((size_t)(pix)) << 8) + lane * 8);                    \
                const __half2* hp = reinterpret_cast<const __half2*>(&v);       \
                float2 f0 = __half22float2(hp[0]);                              \
                float2 f1 = __half22float2(hp[1]);                              \
                float2 f2 = __half22float2(hp[2]);                              \
                float2 f3 = __half22float2(hp[3]);                              \
                a0 = fmaf((wt), f0.x, a0); a1 = fmaf((wt), f0.y, a1);           \
                a2 = fmaf((wt), f1.x, a2); a3 = fmaf((wt), f1.y, a3);           \
                a4 = fmaf((wt), f2.x, a4); a5 = fmaf((wt), f2.y, a5);           \
                a6 = fmaf((wt), f3.x, a6); a7 = fmaf((wt), f3.y, a7);           \
            }                                                                   \
        } while (0)

        #pragma unroll
        for (int sy = 0; sy < 2; sy++) {
            float y = y1s + ((float)ph + (sy ? 0.75f : 0.25f)) * bin_h;
            bool vy = (y > -1.0f) && (y < (float)Hc);
            float yc = fminf(fmaxf(y, 0.0f), (float)(Hc - 1));
            int y0 = (int)floorf(yc);
            int y1b = min(y0 + 1, Hc - 1);
            float ly = yc - (float)y0;
            float hy = 1.0f - ly;

            int rb0 = (b * Hc + y0)  * Wc;
            int rb1 = (b * Hc + y1b) * Wc;

            #pragma unroll
            for (int sx = 0; sx < 2; sx++) {
                float wq = (vy && vx[sx]) ? 1.0f : 0.0f;   // warp-uniform
                float w00 = wq * hy * hx[sx];
                float w01 = wq * hy * lx[sx];
                float w10 = wq * ly * hx[sx];
                float w11 = wq * ly * lx[sx];
                TAP(rb0 + xi0[sx], w00);
                TAP(rb0 + xi1[sx], w01);
                TAP(rb1 + xi0[sx], w10);
                TAP(rb1 + xi1[sx], w11);
            }
        }
        #undef TAP

        // mean over 4 samples; stash in smem as (pw, c)
        float4 lo = make_float4(a0 * 0.25f, a1 * 0.25f, a2 * 0.25f, a3 * 0.25f);
        float4 hi = make_float4(a4 * 0.25f, a5 * 0.25f, a6 * 0.25f, a7 * 0.25f);
        *reinterpret_cast<float4*>(&s[pw][lane * 8])     = lo;
        *reinterpret_cast<float4*>(&s[pw][lane * 8 + 4]) = hi;
    }

    __syncthreads();

    // output: out[(n*C + c)*196 + ph*14 + pw]; 14-float runs per channel row
    for (int c = threadIdx.x; c < Cc; c += 224) {
        size_t o = ((size_t)n * Cc + c) * (PH * PW) + ph * PW;
        #pragma unroll
        for (int p = 0; p < 7; p++) {
            float2 v = make_float2(s[2 * p][c], s[2 * p + 1][c]);
            *reinterpret_cast<float2*>(out + o + 2 * p) = v;   // 8B aligned
        }
    }
}

extern "C" void kernel_launch(void* const* d_in, const int* in_sizes, int n_in,
                              void* d_out, int out_size)
{
    const float* feat = (const float*)d_in[0];
    const float* rois = (const float*)d_in[1];
    float* out = (float*)d_out;

    int K = in_sizes[1] / 5;

    dim3 tg(Wc / 16, Hc, Bc);          // 17 x 200 x 2
    transpose_kernel<<<tg, 256>>>(feat);

    dim3 gg(K, PH);                    // 256 x 14
    gather_kernel<<<gg, 224>>>(rois, out);
}